// round 4
// baseline (speedup 1.0000x reference)
#include <cuda_runtime.h>
#include <math.h>

// Problem constants
#define Bq 512
#define Tt 10
#define Nn 50
#define Hh 200
#define Ee 10000
#define Rr 200
#define H3 600
#define BE (Bq*Ee)

// ---------------- scratch (static __device__, no allocations) ----------------
__device__ float g_proj_s[Ee*Hh];
__device__ float g_proj_o[Ee*Hh];
__device__ float g_bias_s[Bq*Hh];
__device__ float g_bias_o[Bq*Hh];
__device__ float g_seq_s[Bq*Tt*H3];
__device__ float g_seq_o[Bq*Tt*H3];
__device__ float g_gi_s[Bq*Tt*H3];
__device__ float g_gi_o[Bq*Tt*H3];
__device__ float g_gh_s[Bq*H3];
__device__ float g_gh_o[Bq*H3];
__device__ float g_h_s[Bq*Hh];
__device__ float g_h_o[Bq*Hh];
__device__ float g_feat_s[Bq*H3];
__device__ float g_feat_o[Bq*H3];
__device__ float g_lp0[Bq];
__device__ float g_lp1[Bq];
__device__ int   g_sidx[Bq];
__device__ int   g_oidx[Bq];

__device__ __forceinline__ float tanh_fast(float x) {
    float y;
    asm("tanh.approx.f32 %0, %1;" : "=f"(y) : "f"(x));
    return y;
}

// ---------------- parallel stable descending argsort (rank-based) ------------
__global__ void sort_kernel(const int* __restrict__ s_hlen, const int* __restrict__ o_hlen)
{
    int t = threadIdx.x;              // 1024 threads: [0,512) -> s, [512,1024) -> o
    int b = t & 511;
    const int* L = (t < 512) ? s_hlen : o_hlen;
    int lv = L[b];
    int r = 0;
    for (int j = 0; j < Bq; j++) {
        int v = L[j];
        r += (v > lv) || (v == lv && j < b);
    }
    if (t < 512) g_sidx[r] = b; else g_oidx[r] = b;
}

__global__ void init_kernel()
{
    int i = blockIdx.x * blockDim.x + threadIdx.x;
    if (i < Bq*Hh) { g_h_s[i] = 0.f; g_h_o[i] = 0.f; }
}

// ---------------- big fp32 GEMM: C[M,N] = A[M,K] @ W[N,K]^T (+bias) ----------
// 128x128 tile, 8x8 per thread, 256 threads, BK=8, double-buffered smem.
// Requires K % 8 == 0 and 16B-aligned rows (K, lda, ldw all give 16B rows here).
__global__ __launch_bounds__(256, 2)
void gemm128(const float* __restrict__ A, int lda,
             const float* __restrict__ W, int ldw,
             const float* __restrict__ bias,
             float* __restrict__ C, int ldc,
             int M, int N, int K)
{
    __shared__ float As[2][8][132];
    __shared__ float Ws[2][8][132];
    const int tid = threadIdx.x;
    const int bm = blockIdx.y * 128, bn = blockIdx.x * 128;
    const int tx = tid & 15, ty = tid >> 4;        // 16x16 thread grid of 8x8 microtiles
    const int lrow = tid >> 1;                     // 0..127
    const int lc4  = (tid & 1) * 4;                // 0 or 4

    const int gmA = bm + lrow;
    const int gnW = bn + lrow;
    const bool aOk = (gmA < M);
    const bool wOk = (gnW < N);
    const float* Aptr = A + (size_t)gmA * lda + lc4;
    const float* Wptr = W + (size_t)gnW * ldw + lc4;

    float acc[8][8];
#pragma unroll
    for (int i = 0; i < 8; i++)
#pragma unroll
        for (int j = 0; j < 8; j++) acc[i][j] = 0.f;

    const int nt = K >> 3;   // K/8 tiles
    float4 aReg, wReg;
    // prologue: load tile 0
    aReg = aOk ? *reinterpret_cast<const float4*>(Aptr) : make_float4(0,0,0,0);
    wReg = wOk ? *reinterpret_cast<const float4*>(Wptr) : make_float4(0,0,0,0);
    As[0][lc4+0][lrow] = aReg.x; As[0][lc4+1][lrow] = aReg.y;
    As[0][lc4+2][lrow] = aReg.z; As[0][lc4+3][lrow] = aReg.w;
    Ws[0][lc4+0][lrow] = wReg.x; Ws[0][lc4+1][lrow] = wReg.y;
    Ws[0][lc4+2][lrow] = wReg.z; Ws[0][lc4+3][lrow] = wReg.w;
    __syncthreads();

    int buf = 0;
    for (int kt = 0; kt < nt; kt++) {
        const bool more = (kt + 1 < nt);
        if (more) {
            int k0 = (kt + 1) << 3;
            aReg = aOk ? *reinterpret_cast<const float4*>(Aptr + k0) : make_float4(0,0,0,0);
            wReg = wOk ? *reinterpret_cast<const float4*>(Wptr + k0) : make_float4(0,0,0,0);
        }
#pragma unroll
        for (int k = 0; k < 8; k++) {
            float4 a0 = *reinterpret_cast<const float4*>(&As[buf][k][ty * 8]);
            float4 a1 = *reinterpret_cast<const float4*>(&As[buf][k][ty * 8 + 4]);
            float4 b0 = *reinterpret_cast<const float4*>(&Ws[buf][k][tx * 8]);
            float4 b1 = *reinterpret_cast<const float4*>(&Ws[buf][k][tx * 8 + 4]);
            float a[8] = {a0.x,a0.y,a0.z,a0.w,a1.x,a1.y,a1.z,a1.w};
            float b[8] = {b0.x,b0.y,b0.z,b0.w,b1.x,b1.y,b1.z,b1.w};
#pragma unroll
            for (int i = 0; i < 8; i++)
#pragma unroll
                for (int j = 0; j < 8; j++) acc[i][j] += a[i] * b[j];
        }
        if (more) {
            int nb = buf ^ 1;
            As[nb][lc4+0][lrow] = aReg.x; As[nb][lc4+1][lrow] = aReg.y;
            As[nb][lc4+2][lrow] = aReg.z; As[nb][lc4+3][lrow] = aReg.w;
            Ws[nb][lc4+0][lrow] = wReg.x; Ws[nb][lc4+1][lrow] = wReg.y;
            Ws[nb][lc4+2][lrow] = wReg.z; Ws[nb][lc4+3][lrow] = wReg.w;
            __syncthreads();
            buf = nb;
        }
    }

#pragma unroll
    for (int i = 0; i < 8; i++) {
        int gm = bm + ty * 8 + i;
        if (gm >= M) continue;
#pragma unroll
        for (int j = 0; j < 8; j++) {
            int gn = bn + tx * 8 + j;
            if (gn < N)
                C[(size_t)gm * ldc + gn] = acc[i][j] + (bias ? bias[gn] : 0.f);
        }
    }
}

// ---------------- 64x64 GEMM body for the GRU recurrent matmul ---------------
__device__ __forceinline__
void gemm64_body(const float* __restrict__ A, int lda,
                 const float* __restrict__ W, int ldw,
                 const float* __restrict__ bias,
                 float* __restrict__ C, int ldc,
                 int M, int N, int K)
{
    __shared__ float As[16][68];
    __shared__ float Ws[16][68];
    const int tid = threadIdx.x;
    const int tx = tid & 15, ty = tid >> 4;
    const int bm = blockIdx.y * 64, bn = blockIdx.x * 64;

    float acc[4][4];
#pragma unroll
    for (int i = 0; i < 4; i++)
#pragma unroll
        for (int j = 0; j < 4; j++) acc[i][j] = 0.f;

    for (int k0 = 0; k0 < K; k0 += 16) {
#pragma unroll
        for (int l = 0; l < 4; l++) {
            int i = tid + l * 256;
            int m = i >> 4, k = i & 15;
            int gm = bm + m, gk = k0 + k;
            As[k][m] = (gm < M && gk < K) ? A[(size_t)gm * lda + gk] : 0.f;
            int gn = bn + m;
            Ws[k][m] = (gn < N && gk < K) ? W[(size_t)gn * ldw + gk] : 0.f;
        }
        __syncthreads();
#pragma unroll
        for (int k = 0; k < 16; k++) {
            float4 av = *reinterpret_cast<const float4*>(&As[k][ty << 2]);
            float4 bv = *reinterpret_cast<const float4*>(&Ws[k][tx << 2]);
            float a[4] = {av.x, av.y, av.z, av.w};
            float bb[4] = {bv.x, bv.y, bv.z, bv.w};
#pragma unroll
            for (int i = 0; i < 4; i++)
#pragma unroll
                for (int j = 0; j < 4; j++) acc[i][j] += a[i] * bb[j];
        }
        __syncthreads();
    }
#pragma unroll
    for (int i = 0; i < 4; i++) {
        int gm = bm + (ty << 2) + i;
        if (gm >= M) continue;
#pragma unroll
        for (int j = 0; j < 4; j++) {
            int gn = bn + (tx << 2) + j;
            if (gn < N)
                C[(size_t)gm * ldc + gn] = acc[i][j] + (bias ? bias[gn] : 0.f);
        }
    }
}

// GRU gh GEMM for BOTH streams in one launch (blockIdx.z: 0=s, 1=o)
__global__ void gru_gemm2(const float* __restrict__ Whh_s, const float* __restrict__ bhh_s,
                          const float* __restrict__ Whh_o, const float* __restrict__ bhh_o)
{
    if (blockIdx.z == 0)
        gemm64_body(g_h_s, Hh, Whh_s, Hh, bhh_s, g_gh_s, H3, Bq, H3, Hh);
    else
        gemm64_body(g_h_o, Hh, Whh_o, Hh, bhh_o, g_gh_o, H3, Bq, H3, Hh);
}

// ---------------- per-batch attention bias: ba + se@Ws^T + re@Wr^T -----------
__global__ void bias_kernel(const int* __restrict__ trip, int scol,
                            const float* __restrict__ ent,
                            const float* __restrict__ Wa,  // (H, 3H) row-major
                            const float* __restrict__ ba,
                            float* __restrict__ bias)
{
    int b = blockIdx.x;
    __shared__ float se[Hh], re[Hh];
    int tid = threadIdx.x;
    int sid = trip[b * 3 + scol], rid = trip[b * 3 + 1];
    for (int h = tid; h < Hh; h += 256) {
        se[h] = ent[(size_t)sid * Hh + h];
        re[h] = ent[(size_t)rid * Hh + h];
    }
    __syncthreads();
    for (int g = tid; g < Hh; g += 256) {
        const float* wrow = Wa + (size_t)g * H3;
        float acc = ba[g];
#pragma unroll 4
        for (int h = 0; h < Hh; h++)
            acc += se[h] * wrow[Hh + h] + re[h] * wrow[2 * Hh + h];
        bias[b * Hh + g] = acc;
    }
}

// ---------------- attention + softmax + weighted sum + seq assembly ----------
__global__ void attn_kernel(const int* __restrict__ neigh, const int* __restrict__ nlen,
                            const int* __restrict__ hlen, const int* __restrict__ trip,
                            int scol,
                            const float* __restrict__ ent, const float* __restrict__ rel,
                            const float* __restrict__ proj, const float* __restrict__ bias,
                            const float* __restrict__ v, float* __restrict__ seq)
{
    const int bt = blockIdx.x;
    const int b = bt / Tt, t = bt % Tt;
    __shared__ float s_bias[Hh], s_v[Hh];
    __shared__ float s_logit[Nn], s_w[Nn];
    __shared__ int s_nidx[Nn];
    const int tid = threadIdx.x;
    for (int g = tid; g < Hh; g += 256) { s_bias[g] = bias[b * Hh + g]; s_v[g] = v[g]; }
    for (int n = tid; n < Nn; n += 256) s_nidx[n] = neigh[((size_t)b * Tt + t) * Nn + n];
    __syncthreads();
    const int nl = nlen[b * Tt + t];
    const int warp = tid >> 5, lane = tid & 31;
    for (int n = warp; n < nl; n += 8) {
        const float* pr = proj + (size_t)s_nidx[n] * Hh;
        float acc = 0.f;
        for (int g = lane; g < Hh; g += 32)
            acc += tanh_fast(pr[g] + s_bias[g]) * s_v[g];
        for (int o = 16; o; o >>= 1) acc += __shfl_xor_sync(0xffffffffu, acc, o);
        if (lane == 0) s_logit[n] = acc;
    }
    __syncthreads();
    if (warp == 0) {
        float m = -3.4e38f;
        for (int n = lane; n < nl; n += 32) m = fmaxf(m, s_logit[n]);
        for (int o = 16; o; o >>= 1) m = fmaxf(m, __shfl_xor_sync(0xffffffffu, m, o));
        float s = 0.f;
        for (int n = lane; n < nl; n += 32) { float e = expf(s_logit[n] - m); s_w[n] = e; s += e; }
        for (int o = 16; o; o >>= 1) s += __shfl_xor_sync(0xffffffffu, s, o);
        float inv = 1.f / s;
        for (int n = lane; n < nl; n += 32) s_w[n] *= inv;
    }
    __syncthreads();
    const float msk = (t < hlen[b]) ? 1.f : 0.f;
    const int sid = trip[b * 3 + scol], rid = trip[b * 3 + 1];
    float* out = seq + ((size_t)b * Tt + t) * H3;
    for (int h = tid; h < Hh; h += 256) {
        float acc = 0.f;
        for (int n = 0; n < nl; n++) acc += s_w[n] * ent[(size_t)s_nidx[n] * Hh + h];
        out[h] = acc * msk;
        out[Hh + h] = ent[(size_t)sid * Hh + h] * msk;
        out[2 * Hh + h] = rel[(size_t)rid * Hh + h] * msk;
    }
}

// ---------------- GRU pointwise update for BOTH streams ----------------------
__global__ void gru_update2(const int* __restrict__ slen, const int* __restrict__ olen, int t)
{
    int b = blockIdx.x;
    int j = threadIdx.x;
    if (j >= Hh) return;
    const float* gi;
    const float* gh;
    float* h;
    const int* len;
    if (blockIdx.z == 0) { gi = g_gi_s; gh = g_gh_s; h = g_h_s; len = slen; }
    else                 { gi = g_gi_o; gh = g_gh_o; h = g_h_o; len = olen; }
    if (t >= len[b]) return;   // masked step: h unchanged
    const float* gib = gi + ((size_t)b * Tt + t) * H3;
    const float* ghb = gh + (size_t)b * H3;
    float ir = gib[j], iz = gib[Hh + j], inn = gib[2 * Hh + j];
    float hr = ghb[j], hz = ghb[Hh + j], hn = ghb[2 * Hh + j];
    float rg = 1.f / (1.f + expf(-(ir + hr)));
    float zg = 1.f / (1.f + expf(-(iz + hz)));
    float ng = tanhf(inn + rg * hn);
    float hp = h[(size_t)b * Hh + j];
    h[(size_t)b * Hh + j] = (1.f - zg) * ng + zg * hp;
}

// ---------------- final feature assembly (permuted by idx) -------------------
__global__ void feat_kernel(const int* __restrict__ trip, const int* __restrict__ idx,
                            int scol, const float* __restrict__ ent,
                            const float* __restrict__ rel, const float* __restrict__ h,
                            float* __restrict__ feat)
{
    int b = blockIdx.x;
    int p = idx[b];
    int sid = trip[p * 3 + scol], rid = trip[p * 3 + 1];
    for (int i = threadIdx.x; i < Hh; i += 256) {
        feat[(size_t)b * H3 + i]          = ent[(size_t)sid * Hh + i];
        feat[(size_t)b * H3 + Hh + i]     = h[(size_t)p * Hh + i];
        feat[(size_t)b * H3 + 2*Hh + i]   = rel[(size_t)rid * Hh + i];
    }
}

// ---------------- cross-entropy per-row log-prob of label --------------------
__global__ void ce_kernel(const float* __restrict__ pred, const int* __restrict__ trip,
                          const int* __restrict__ idx, int labcol, float* __restrict__ lp)
{
    int b = blockIdx.x;
    const float* row = pred + (size_t)b * Ee;
    int tid = threadIdx.x;
    int lane = tid & 31, warp = tid >> 5;
    __shared__ float sred[8];

    float m = -3.4e38f;
    for (int i = tid; i < Ee; i += 256) m = fmaxf(m, row[i]);
    for (int o = 16; o; o >>= 1) m = fmaxf(m, __shfl_xor_sync(0xffffffffu, m, o));
    if (lane == 0) sred[warp] = m;
    __syncthreads();
    if (tid == 0) {
        float mm = sred[0];
        for (int i = 1; i < 8; i++) mm = fmaxf(mm, sred[i]);
        sred[0] = mm;
    }
    __syncthreads();
    m = sred[0];
    __syncthreads();

    float s = 0.f;
    for (int i = tid; i < Ee; i += 256) s += expf(row[i] - m);
    for (int o = 16; o; o >>= 1) s += __shfl_xor_sync(0xffffffffu, s, o);
    if (lane == 0) sred[warp] = s;
    __syncthreads();
    if (tid == 0) {
        float st = 0.f;
        for (int i = 0; i < 8; i++) st += sred[i];
        int lab = trip[idx[b] * 3 + labcol];
        lp[b] = row[lab] - m - logf(st);
    }
}

// ---------------- finalize: loss + index outputs ------------------------------
__global__ void finalize_kernel(float* __restrict__ out)
{
    int tid = threadIdx.x;
    if (tid == 0) {
        double a = 0.0, c = 0.0;
        for (int b = 0; b < Bq; b++) { a += (double)g_lp0[b]; c += (double)g_lp1[b]; }
        out[0] = (float)(-(a / (double)Bq) - (c / (double)Bq));
    }
    for (int b = tid; b < Bq; b += blockDim.x) {
        out[1 + 2 * (size_t)BE + b]       = (float)g_oidx[b];
        out[1 + 2 * (size_t)BE + Bq + b]  = (float)g_sidx[b];
    }
}

// ---------------- host-side orchestration ------------------------------------
extern "C" void kernel_launch(void* const* d_in, const int* in_sizes, int n_in,
                              void* d_out, int out_size)
{
    const int*   trip     = (const int*)d_in[0];
    const int*   s_neigh  = (const int*)d_in[1];
    const int*   s_nlen   = (const int*)d_in[2];
    const int*   s_hlen   = (const int*)d_in[3];
    const int*   o_neigh  = (const int*)d_in[4];
    const int*   o_nlen   = (const int*)d_in[5];
    const int*   o_hlen   = (const int*)d_in[6];
    const float* ent      = (const float*)d_in[7];
    const float* rel      = (const float*)d_in[8];
    const float* attn_s_w = (const float*)d_in[9];
    const float* attn_s_b = (const float*)d_in[10];
    const float* v_s      = (const float*)d_in[11];
    const float* attn_o_w = (const float*)d_in[12];
    const float* attn_o_b = (const float*)d_in[13];
    const float* v_o      = (const float*)d_in[14];
    const float* sub_w_ih = (const float*)d_in[15];
    const float* sub_w_hh = (const float*)d_in[16];
    const float* sub_b_ih = (const float*)d_in[17];
    const float* sub_b_hh = (const float*)d_in[18];
    const float* ob_w_ih  = (const float*)d_in[19];
    const float* ob_w_hh  = (const float*)d_in[20];
    const float* ob_b_ih  = (const float*)d_in[21];
    const float* ob_b_hh  = (const float*)d_in[22];
    const float* lin_sub_w = (const float*)d_in[23];
    const float* lin_sub_b = (const float*)d_in[24];
    const float* lin_ob_w  = (const float*)d_in[25];
    const float* lin_ob_b  = (const float*)d_in[26];
    float* out = (float*)d_out;

    float *proj_s, *proj_o, *bias_s, *bias_o, *seq_s, *seq_o, *gi_s, *gi_o;
    float *h_s, *h_o, *feat_s, *feat_o, *lp0, *lp1;
    int *sidx, *oidx;
    cudaGetSymbolAddress((void**)&proj_s, g_proj_s);
    cudaGetSymbolAddress((void**)&proj_o, g_proj_o);
    cudaGetSymbolAddress((void**)&bias_s, g_bias_s);
    cudaGetSymbolAddress((void**)&bias_o, g_bias_o);
    cudaGetSymbolAddress((void**)&seq_s,  g_seq_s);
    cudaGetSymbolAddress((void**)&seq_o,  g_seq_o);
    cudaGetSymbolAddress((void**)&gi_s,   g_gi_s);
    cudaGetSymbolAddress((void**)&gi_o,   g_gi_o);
    cudaGetSymbolAddress((void**)&h_s,    g_h_s);
    cudaGetSymbolAddress((void**)&h_o,    g_h_o);
    cudaGetSymbolAddress((void**)&feat_s, g_feat_s);
    cudaGetSymbolAddress((void**)&feat_o, g_feat_o);
    cudaGetSymbolAddress((void**)&lp0,    g_lp0);
    cudaGetSymbolAddress((void**)&lp1,    g_lp1);
    cudaGetSymbolAddress((void**)&sidx,   g_sidx);
    cudaGetSymbolAddress((void**)&oidx,   g_oidx);

    // 1) parallel stable descending argsort + h0 = 0
    sort_kernel<<<1, 1024>>>(s_hlen, o_hlen);
    init_kernel<<<(Bq * Hh + 255) / 256, 256>>>();

    // 2) entity projections through Wn (attn weight cols [0:H))
    //    M=Ee rows, N=Hh cols, K=Hh
    dim3 gProj((Hh + 127) / 128, (Ee + 127) / 128);
    gemm128<<<gProj, 256>>>(ent, Hh, attn_s_w, H3, nullptr, proj_s, Hh, Ee, Hh, Hh);
    gemm128<<<gProj, 256>>>(ent, Hh, attn_o_w, H3, nullptr, proj_o, Hh, Ee, Hh, Hh);

    // 3) per-batch bias terms (se@Ws^T + re@Wr^T + ba)
    bias_kernel<<<Bq, 256>>>(trip, 0, ent, attn_s_w, attn_s_b, bias_s);
    bias_kernel<<<Bq, 256>>>(trip, 2, ent, attn_o_w, attn_o_b, bias_o);

    // 4) attention + softmax + weighted neighbor sum + seq assembly
    attn_kernel<<<Bq * Tt, 256>>>(s_neigh, s_nlen, s_hlen, trip, 0, ent, rel,
                                  proj_s, bias_s, v_s, seq_s);
    attn_kernel<<<Bq * Tt, 256>>>(o_neigh, o_nlen, o_hlen, trip, 2, ent, rel,
                                  proj_o, bias_o, v_o, seq_o);

    // 5) GRU input gates for all timesteps at once
    dim3 gGi((H3 + 127) / 128, (Bq * Tt + 127) / 128);
    gemm128<<<gGi, 256>>>(seq_s, H3, sub_w_ih, H3, sub_b_ih, gi_s, H3, Bq * Tt, H3, H3);
    gemm128<<<gGi, 256>>>(seq_o, H3, ob_w_ih,  H3, ob_b_ih,  gi_o, H3, Bq * Tt, H3, H3);

    // 6) sequential GRU steps — both streams in one launch per phase
    dim3 gGh((H3 + 63) / 64, (Bq + 63) / 64, 2);
    dim3 gUp(Bq, 1, 2);
    for (int t = 0; t < Tt; t++) {
        gru_gemm2<<<gGh, 256>>>(sub_w_hh, sub_b_hh, ob_w_hh, ob_b_hh);
        gru_update2<<<gUp, 256>>>(s_hlen, o_hlen, t);
    }

    // 7) permuted feature assembly
    feat_kernel<<<Bq, 256>>>(trip, sidx, 0, ent, rel, h_s, feat_s);
    feat_kernel<<<Bq, 256>>>(trip, oidx, 2, ent, rel, h_o, feat_o);

    // 8) prediction GEMMs directly into d_out
    //    layout: [loss(1) | sub_pred(B*E) | ob_pred(B*E) | o_idx(B) | s_idx(B)]
    dim3 gPred((Ee + 127) / 128, (Bq + 127) / 128);
    gemm128<<<gPred, 256>>>(feat_s, H3, lin_sub_w, H3, lin_sub_b,
                            out + 1 + (size_t)BE, Ee, Bq, Ee, H3);   // ob_pred
    gemm128<<<gPred, 256>>>(feat_o, H3, lin_ob_w, H3, lin_ob_b,
                            out + 1, Ee, Bq, Ee, H3);                // sub_pred

    // 9) CE log-probs + finalize (deterministic fixed-order sum)
    ce_kernel<<<Bq, 256>>>(out + 1 + (size_t)BE, trip, sidx, 2, lp0); // ob_pred vs o[s_idx]
    ce_kernel<<<Bq, 256>>>(out + 1,              trip, oidx, 0, lp1); // sub_pred vs s[o_idx]
    finalize_kernel<<<1, 512>>>(out);
}

// round 6
// speedup vs baseline: 2.5235x; 2.5235x over previous
#include <cuda_runtime.h>
#include <math.h>
#include <stdint.h>

// Problem constants
#define Bq 512
#define Tt 10
#define Nn 50
#define Hh 200
#define Ee 10000
#define Rr 200
#define H3 600
#define BE (Bq*Ee)

// ---------------- scratch (static __device__, no allocations) ----------------
__device__ float g_proj_s[Ee*Hh];
__device__ float g_proj_o[Ee*Hh];
__device__ float g_bias_s[Bq*Hh];
__device__ float g_bias_o[Bq*Hh];
__device__ float g_seq_s[Bq*Tt*H3];
__device__ float g_seq_o[Bq*Tt*H3];
__device__ float g_gi_s[Bq*Tt*H3];
__device__ float g_gi_o[Bq*Tt*H3];
__device__ float g_gh_s[Bq*H3];
__device__ float g_gh_o[Bq*H3];
__device__ float g_h_s[Bq*Hh];
__device__ float g_h_o[Bq*Hh];
__device__ float g_feat_s[Bq*H3];
__device__ float g_feat_o[Bq*H3];
__device__ float g_lp0[Bq];
__device__ float g_lp1[Bq];
__device__ int   g_sidx[Bq];
__device__ int   g_oidx[Bq];

__device__ __forceinline__ float tanh_fast(float x) {
    float y;
    asm("tanh.approx.f32 %0, %1;" : "=f"(y) : "f"(x));
    return y;
}

__device__ __forceinline__ uint32_t cvt_tf32(float x) {
    uint32_t y;
    asm("cvt.rna.tf32.f32 %0, %1;" : "=r"(y) : "f"(x));
    return y;
}

__device__ __forceinline__ void mma_tf32(float* d, const uint32_t* a, const uint32_t* b) {
    asm volatile(
        "mma.sync.aligned.m16n8k8.row.col.f32.tf32.tf32.f32 "
        "{%0,%1,%2,%3}, {%4,%5,%6,%7}, {%8,%9}, {%0,%1,%2,%3};"
        : "+f"(d[0]), "+f"(d[1]), "+f"(d[2]), "+f"(d[3])
        : "r"(a[0]), "r"(a[1]), "r"(a[2]), "r"(a[3]), "r"(b[0]), "r"(b[1]));
}

// ---------------- parallel stable descending argsort (rank-based) ------------
__global__ void sort_kernel(const int* __restrict__ s_hlen, const int* __restrict__ o_hlen)
{
    int t = threadIdx.x;              // 1024 threads: [0,512) -> s, [512,1024) -> o
    int b = t & 511;
    const int* L = (t < 512) ? s_hlen : o_hlen;
    int lv = L[b];
    int r = 0;
    for (int j = 0; j < Bq; j++) {
        int v = L[j];
        r += (v > lv) || (v == lv && j < b);
    }
    if (t < 512) g_sidx[r] = b; else g_oidx[r] = b;
}

__global__ void init_kernel()
{
    int i = blockIdx.x * blockDim.x + threadIdx.x;
    if (i < Bq*Hh) { g_h_s[i] = 0.f; g_h_o[i] = 0.f; }
}

// ============ tf32 tensor-core GEMM: C[M,N] = A[M,K] @ W[N,K]^T (+bias) ======
// CTA tile 128(M) x 64(N), 8 warps (4x2), warp tile 32x32 = 2x4 m16n8k8 frags.
// BK=8, double-buffered smem. Requires K % 8 == 0, A/W rows 16B-aligned.
// C stores are SCALAR (C may be arbitrarily offset, e.g. d_out+1).
__device__ __forceinline__
void gemm_tc_body(const float* __restrict__ A, int lda,
                  const float* __restrict__ W, int ldw,
                  const float* __restrict__ bias,
                  float* __restrict__ C, int ldc,
                  int M, int N, int K)
{
    __shared__ uint32_t As[2][8][132];
    __shared__ uint32_t Ws[2][8][68];

    const int tid  = threadIdx.x;
    const int bm   = blockIdx.y * 128;
    const int bn   = blockIdx.x * 64;
    const int wid  = tid >> 5, lane = tid & 31;
    const int gid  = lane >> 2, tig = lane & 3;
    const int wm   = (wid & 3) * 32;     // warp M offset in CTA tile
    const int wn   = (wid >> 2) * 32;    // warp N offset

    // staging indices
    const int sm   = tid >> 1;           // 0..127 (A row in tile)
    const int skq  = (tid & 1) * 4;      // 0 or 4 (k quad)
    const bool aOk = (bm + sm) < M;
    const float* Aptr = A + (size_t)(bm + sm) * lda + skq;
    const int  swn  = tid >> 1;          // for tid<128: W row 0..63
    const bool wOk = (tid < 128) && ((bn + swn) < N);
    const float* Wptr = W + (size_t)(bn + swn) * ldw + skq;

    float acc[2][4][4];
#pragma unroll
    for (int i = 0; i < 2; i++)
#pragma unroll
        for (int j = 0; j < 4; j++)
#pragma unroll
            for (int e = 0; e < 4; e++) acc[i][j][e] = 0.f;

    const int nt = K >> 3;

    // prologue: stage tile 0
    {
        float4 av = aOk ? *(const float4*)(Aptr) : make_float4(0,0,0,0);
        As[0][skq+0][sm] = cvt_tf32(av.x);
        As[0][skq+1][sm] = cvt_tf32(av.y);
        As[0][skq+2][sm] = cvt_tf32(av.z);
        As[0][skq+3][sm] = cvt_tf32(av.w);
        if (tid < 128) {
            float4 wv = wOk ? *(const float4*)(Wptr) : make_float4(0,0,0,0);
            Ws[0][skq+0][swn] = cvt_tf32(wv.x);
            Ws[0][skq+1][swn] = cvt_tf32(wv.y);
            Ws[0][skq+2][swn] = cvt_tf32(wv.z);
            Ws[0][skq+3][swn] = cvt_tf32(wv.w);
        }
    }
    __syncthreads();

    for (int kt = 0; kt < nt; kt++) {
        const int buf = kt & 1;
        const bool more = (kt + 1) < nt;
        float4 av, wv;
        if (more) {
            int k0 = (kt + 1) << 3;
            av = aOk ? *(const float4*)(Aptr + k0) : make_float4(0,0,0,0);
            if (tid < 128)
                wv = wOk ? *(const float4*)(Wptr + k0) : make_float4(0,0,0,0);
        }

        // load fragments
        uint32_t afr[2][4], bfr[4][2];
#pragma unroll
        for (int i = 0; i < 2; i++) {
            int mb = wm + 16 * i + gid;
            afr[i][0] = As[buf][tig    ][mb    ];
            afr[i][1] = As[buf][tig    ][mb + 8];
            afr[i][2] = As[buf][tig + 4][mb    ];
            afr[i][3] = As[buf][tig + 4][mb + 8];
        }
#pragma unroll
        for (int j = 0; j < 4; j++) {
            int nb = wn + 8 * j + gid;
            bfr[j][0] = Ws[buf][tig    ][nb];
            bfr[j][1] = Ws[buf][tig + 4][nb];
        }
#pragma unroll
        for (int i = 0; i < 2; i++)
#pragma unroll
            for (int j = 0; j < 4; j++)
                mma_tf32(acc[i][j], afr[i], bfr[j]);

        if (more) {
            const int nbuf = buf ^ 1;
            As[nbuf][skq+0][sm] = cvt_tf32(av.x);
            As[nbuf][skq+1][sm] = cvt_tf32(av.y);
            As[nbuf][skq+2][sm] = cvt_tf32(av.z);
            As[nbuf][skq+3][sm] = cvt_tf32(av.w);
            if (tid < 128) {
                Ws[nbuf][skq+0][swn] = cvt_tf32(wv.x);
                Ws[nbuf][skq+1][swn] = cvt_tf32(wv.y);
                Ws[nbuf][skq+2][swn] = cvt_tf32(wv.z);
                Ws[nbuf][skq+3][swn] = cvt_tf32(wv.w);
            }
            __syncthreads();
        }
    }

    // epilogue (scalar stores — C may be misaligned for vector access)
#pragma unroll
    for (int i = 0; i < 2; i++) {
        int r0 = bm + wm + 16 * i + gid;
        int r1 = r0 + 8;
#pragma unroll
        for (int j = 0; j < 4; j++) {
            int c = bn + wn + 8 * j + 2 * tig;
            if (c < N) {   // N even in all our calls -> c+1 < N too
                float b0 = bias ? bias[c]     : 0.f;
                float b1 = bias ? bias[c + 1] : 0.f;
                if (r0 < M) {
                    C[(size_t)r0 * ldc + c]     = acc[i][j][0] + b0;
                    C[(size_t)r0 * ldc + c + 1] = acc[i][j][1] + b1;
                }
                if (r1 < M) {
                    C[(size_t)r1 * ldc + c]     = acc[i][j][2] + b0;
                    C[(size_t)r1 * ldc + c + 1] = acc[i][j][3] + b1;
                }
            }
        }
    }
}

__global__ __launch_bounds__(256)
void gemm_tc(const float* __restrict__ A, int lda,
             const float* __restrict__ W, int ldw,
             const float* __restrict__ bias,
             float* __restrict__ C, int ldc,
             int M, int N, int K)
{
    gemm_tc_body(A, lda, W, ldw, bias, C, ldc, M, N, K);
}

// GRU gh GEMM for BOTH streams in one launch (blockIdx.z: 0=s, 1=o)
__global__ __launch_bounds__(256)
void gru_gemm2(const float* __restrict__ Whh_s, const float* __restrict__ bhh_s,
               const float* __restrict__ Whh_o, const float* __restrict__ bhh_o)
{
    if (blockIdx.z == 0)
        gemm_tc_body(g_h_s, Hh, Whh_s, Hh, bhh_s, g_gh_s, H3, Bq, H3, Hh);
    else
        gemm_tc_body(g_h_o, Hh, Whh_o, Hh, bhh_o, g_gh_o, H3, Bq, H3, Hh);
}

// ---------------- per-batch attention bias: ba + se@Ws^T + re@Wr^T -----------
__global__ void bias_kernel(const int* __restrict__ trip, int scol,
                            const float* __restrict__ ent,
                            const float* __restrict__ Wa,  // (H, 3H) row-major
                            const float* __restrict__ ba,
                            float* __restrict__ bias)
{
    int b = blockIdx.x;
    __shared__ float se[Hh], re[Hh];
    int tid = threadIdx.x;
    int sid = trip[b * 3 + scol], rid = trip[b * 3 + 1];
    for (int h = tid; h < Hh; h += 256) {
        se[h] = ent[(size_t)sid * Hh + h];
        re[h] = ent[(size_t)rid * Hh + h];
    }
    __syncthreads();
    for (int g = tid; g < Hh; g += 256) {
        const float* wrow = Wa + (size_t)g * H3;
        float acc = ba[g];
#pragma unroll 4
        for (int h = 0; h < Hh; h++)
            acc += se[h] * wrow[Hh + h] + re[h] * wrow[2 * Hh + h];
        bias[b * Hh + g] = acc;
    }
}

// ---------------- attention + softmax + weighted sum + seq assembly ----------
__global__ void attn_kernel(const int* __restrict__ neigh, const int* __restrict__ nlen,
                            const int* __restrict__ hlen, const int* __restrict__ trip,
                            int scol,
                            const float* __restrict__ ent, const float* __restrict__ rel,
                            const float* __restrict__ proj, const float* __restrict__ bias,
                            const float* __restrict__ v, float* __restrict__ seq)
{
    const int bt = blockIdx.x;
    const int b = bt / Tt, t = bt % Tt;
    __shared__ float s_bias[Hh], s_v[Hh];
    __shared__ float s_logit[Nn], s_w[Nn];
    __shared__ int s_nidx[Nn];
    const int tid = threadIdx.x;
    for (int g = tid; g < Hh; g += 256) { s_bias[g] = bias[b * Hh + g]; s_v[g] = v[g]; }
    for (int n = tid; n < Nn; n += 256) s_nidx[n] = neigh[((size_t)b * Tt + t) * Nn + n];
    __syncthreads();
    const int nl = nlen[b * Tt + t];
    const int warp = tid >> 5, lane = tid & 31;
    for (int n = warp; n < nl; n += 8) {
        const float* pr = proj + (size_t)s_nidx[n] * Hh;
        float acc = 0.f;
        for (int g = lane; g < Hh; g += 32)
            acc += tanh_fast(pr[g] + s_bias[g]) * s_v[g];
        for (int o = 16; o; o >>= 1) acc += __shfl_xor_sync(0xffffffffu, acc, o);
        if (lane == 0) s_logit[n] = acc;
    }
    __syncthreads();
    if (warp == 0) {
        float m = -3.4e38f;
        for (int n = lane; n < nl; n += 32) m = fmaxf(m, s_logit[n]);
        for (int o = 16; o; o >>= 1) m = fmaxf(m, __shfl_xor_sync(0xffffffffu, m, o));
        float s = 0.f;
        for (int n = lane; n < nl; n += 32) { float e = expf(s_logit[n] - m); s_w[n] = e; s += e; }
        for (int o = 16; o; o >>= 1) s += __shfl_xor_sync(0xffffffffu, s, o);
        float inv = 1.f / s;
        for (int n = lane; n < nl; n += 32) s_w[n] *= inv;
    }
    __syncthreads();
    const float msk = (t < hlen[b]) ? 1.f : 0.f;
    const int sid = trip[b * 3 + scol], rid = trip[b * 3 + 1];
    float* out = seq + ((size_t)b * Tt + t) * H3;
    for (int h = tid; h < Hh; h += 256) {
        float acc = 0.f;
        for (int n = 0; n < nl; n++) acc += s_w[n] * ent[(size_t)s_nidx[n] * Hh + h];
        out[h] = acc * msk;
        out[Hh + h] = ent[(size_t)sid * Hh + h] * msk;
        out[2 * Hh + h] = rel[(size_t)rid * Hh + h] * msk;
    }
}

// ---------------- GRU pointwise update for BOTH streams ----------------------
__global__ void gru_update2(const int* __restrict__ slen, const int* __restrict__ olen, int t)
{
    int b = blockIdx.x;
    int j = threadIdx.x;
    if (j >= Hh) return;
    const float* gi;
    const float* gh;
    float* h;
    const int* len;
    if (blockIdx.z == 0) { gi = g_gi_s; gh = g_gh_s; h = g_h_s; len = slen; }
    else                 { gi = g_gi_o; gh = g_gh_o; h = g_h_o; len = olen; }
    if (t >= len[b]) return;   // masked step: h unchanged
    const float* gib = gi + ((size_t)b * Tt + t) * H3;
    const float* ghb = gh + (size_t)b * H3;
    float ir = gib[j], iz = gib[Hh + j], inn = gib[2 * Hh + j];
    float hr = ghb[j], hz = ghb[Hh + j], hn = ghb[2 * Hh + j];
    float rg = 1.f / (1.f + expf(-(ir + hr)));
    float zg = 1.f / (1.f + expf(-(iz + hz)));
    float ng = tanhf(inn + rg * hn);
    float hp = h[(size_t)b * Hh + j];
    h[(size_t)b * Hh + j] = (1.f - zg) * ng + zg * hp;
}

// ---------------- final feature assembly (permuted by idx) -------------------
__global__ void feat_kernel(const int* __restrict__ trip, const int* __restrict__ idx,
                            int scol, const float* __restrict__ ent,
                            const float* __restrict__ rel, const float* __restrict__ h,
                            float* __restrict__ feat)
{
    int b = blockIdx.x;
    int p = idx[b];
    int sid = trip[p * 3 + scol], rid = trip[p * 3 + 1];
    for (int i = threadIdx.x; i < Hh; i += 256) {
        feat[(size_t)b * H3 + i]          = ent[(size_t)sid * Hh + i];
        feat[(size_t)b * H3 + Hh + i]     = h[(size_t)p * Hh + i];
        feat[(size_t)b * H3 + 2*Hh + i]   = rel[(size_t)rid * Hh + i];
    }
}

// ---------------- cross-entropy per-row log-prob of label --------------------
__global__ void ce_kernel(const float* __restrict__ pred, const int* __restrict__ trip,
                          const int* __restrict__ idx, int labcol, float* __restrict__ lp)
{
    int b = blockIdx.x;
    const float* row = pred + (size_t)b * Ee;
    int tid = threadIdx.x;
    int lane = tid & 31, warp = tid >> 5;
    __shared__ float sred[8];

    float m = -3.4e38f;
    for (int i = tid; i < Ee; i += 256) m = fmaxf(m, row[i]);
    for (int o = 16; o; o >>= 1) m = fmaxf(m, __shfl_xor_sync(0xffffffffu, m, o));
    if (lane == 0) sred[warp] = m;
    __syncthreads();
    if (tid == 0) {
        float mm = sred[0];
        for (int i = 1; i < 8; i++) mm = fmaxf(mm, sred[i]);
        sred[0] = mm;
    }
    __syncthreads();
    m = sred[0];
    __syncthreads();

    float s = 0.f;
    for (int i = tid; i < Ee; i += 256) s += expf(row[i] - m);
    for (int o = 16; o; o >>= 1) s += __shfl_xor_sync(0xffffffffu, s, o);
    if (lane == 0) sred[warp] = s;
    __syncthreads();
    if (tid == 0) {
        float st = 0.f;
        for (int i = 0; i < 8; i++) st += sred[i];
        int lab = trip[idx[b] * 3 + labcol];
        lp[b] = row[lab] - m - logf(st);
    }
}

// ---------------- finalize: loss + index outputs ------------------------------
__global__ void finalize_kernel(float* __restrict__ out)
{
    int tid = threadIdx.x;
    if (tid == 0) {
        double a = 0.0, c = 0.0;
        for (int b = 0; b < Bq; b++) { a += (double)g_lp0[b]; c += (double)g_lp1[b]; }
        out[0] = (float)(-(a / (double)Bq) - (c / (double)Bq));
    }
    for (int b = tid; b < Bq; b += blockDim.x) {
        out[1 + 2 * (size_t)BE + b]       = (float)g_oidx[b];
        out[1 + 2 * (size_t)BE + Bq + b]  = (float)g_sidx[b];
    }
}

// ---------------- host-side orchestration ------------------------------------
extern "C" void kernel_launch(void* const* d_in, const int* in_sizes, int n_in,
                              void* d_out, int out_size)
{
    const int*   trip     = (const int*)d_in[0];
    const int*   s_neigh  = (const int*)d_in[1];
    const int*   s_nlen   = (const int*)d_in[2];
    const int*   s_hlen   = (const int*)d_in[3];
    const int*   o_neigh  = (const int*)d_in[4];
    const int*   o_nlen   = (const int*)d_in[5];
    const int*   o_hlen   = (const int*)d_in[6];
    const float* ent      = (const float*)d_in[7];
    const float* rel      = (const float*)d_in[8];
    const float* attn_s_w = (const float*)d_in[9];
    const float* attn_s_b = (const float*)d_in[10];
    const float* v_s      = (const float*)d_in[11];
    const float* attn_o_w = (const float*)d_in[12];
    const float* attn_o_b = (const float*)d_in[13];
    const float* v_o      = (const float*)d_in[14];
    const float* sub_w_ih = (const float*)d_in[15];
    const float* sub_w_hh = (const float*)d_in[16];
    const float* sub_b_ih = (const float*)d_in[17];
    const float* sub_b_hh = (const float*)d_in[18];
    const float* ob_w_ih  = (const float*)d_in[19];
    const float* ob_w_hh  = (const float*)d_in[20];
    const float* ob_b_ih  = (const float*)d_in[21];
    const float* ob_b_hh  = (const float*)d_in[22];
    const float* lin_sub_w = (const float*)d_in[23];
    const float* lin_sub_b = (const float*)d_in[24];
    const float* lin_ob_w  = (const float*)d_in[25];
    const float* lin_ob_b  = (const float*)d_in[26];
    float* out = (float*)d_out;

    float *proj_s, *proj_o, *bias_s, *bias_o, *seq_s, *seq_o, *gi_s, *gi_o;
    float *h_s, *h_o, *feat_s, *feat_o, *lp0, *lp1;
    int *sidx, *oidx;
    cudaGetSymbolAddress((void**)&proj_s, g_proj_s);
    cudaGetSymbolAddress((void**)&proj_o, g_proj_o);
    cudaGetSymbolAddress((void**)&bias_s, g_bias_s);
    cudaGetSymbolAddress((void**)&bias_o, g_bias_o);
    cudaGetSymbolAddress((void**)&seq_s,  g_seq_s);
    cudaGetSymbolAddress((void**)&seq_o,  g_seq_o);
    cudaGetSymbolAddress((void**)&gi_s,   g_gi_s);
    cudaGetSymbolAddress((void**)&gi_o,   g_gi_o);
    cudaGetSymbolAddress((void**)&h_s,    g_h_s);
    cudaGetSymbolAddress((void**)&h_o,    g_h_o);
    cudaGetSymbolAddress((void**)&feat_s, g_feat_s);
    cudaGetSymbolAddress((void**)&feat_o, g_feat_o);
    cudaGetSymbolAddress((void**)&lp0,    g_lp0);
    cudaGetSymbolAddress((void**)&lp1,    g_lp1);
    cudaGetSymbolAddress((void**)&sidx,   g_sidx);
    cudaGetSymbolAddress((void**)&oidx,   g_oidx);

    // 1) parallel stable descending argsort + h0 = 0
    sort_kernel<<<1, 1024>>>(s_hlen, o_hlen);
    init_kernel<<<(Bq * Hh + 255) / 256, 256>>>();

    // 2) entity projections through Wn (attn weight cols [0:H))
    //    M=Ee, N=Hh, K=Hh
    dim3 gProj((Hh + 63) / 64, (Ee + 127) / 128);
    gemm_tc<<<gProj, 256>>>(ent, Hh, attn_s_w, H3, nullptr, proj_s, Hh, Ee, Hh, Hh);
    gemm_tc<<<gProj, 256>>>(ent, Hh, attn_o_w, H3, nullptr, proj_o, Hh, Ee, Hh, Hh);

    // 3) per-batch bias terms (se@Ws^T + re@Wr^T + ba)
    bias_kernel<<<Bq, 256>>>(trip, 0, ent, attn_s_w, attn_s_b, bias_s);
    bias_kernel<<<Bq, 256>>>(trip, 2, ent, attn_o_w, attn_o_b, bias_o);

    // 4) attention + softmax + weighted neighbor sum + seq assembly
    attn_kernel<<<Bq * Tt, 256>>>(s_neigh, s_nlen, s_hlen, trip, 0, ent, rel,
                                  proj_s, bias_s, v_s, seq_s);
    attn_kernel<<<Bq * Tt, 256>>>(o_neigh, o_nlen, o_hlen, trip, 2, ent, rel,
                                  proj_o, bias_o, v_o, seq_o);

    // 5) GRU input gates for all timesteps at once (M=B*T, N=3H, K=3H)
    dim3 gGi((H3 + 63) / 64, (Bq * Tt + 127) / 128);
    gemm_tc<<<gGi, 256>>>(seq_s, H3, sub_w_ih, H3, sub_b_ih, gi_s, H3, Bq * Tt, H3, H3);
    gemm_tc<<<gGi, 256>>>(seq_o, H3, ob_w_ih,  H3, ob_b_ih,  gi_o, H3, Bq * Tt, H3, H3);

    // 6) sequential GRU steps — both streams per launch
    dim3 gGh((H3 + 63) / 64, (Bq + 127) / 128, 2);
    dim3 gUp(Bq, 1, 2);
    for (int t = 0; t < Tt; t++) {
        gru_gemm2<<<gGh, 256>>>(sub_w_hh, sub_b_hh, ob_w_hh, ob_b_hh);
        gru_update2<<<gUp, 256>>>(s_hlen, o_hlen, t);
    }

    // 7) permuted feature assembly
    feat_kernel<<<Bq, 256>>>(trip, sidx, 0, ent, rel, h_s, feat_s);
    feat_kernel<<<Bq, 256>>>(trip, oidx, 2, ent, rel, h_o, feat_o);

    // 8) prediction GEMMs directly into d_out (M=Bq, N=Ee, K=3H)
    //    layout: [loss(1) | sub_pred(B*E) | ob_pred(B*E) | o_idx(B) | s_idx(B)]
    dim3 gPred((Ee + 63) / 64, (Bq + 127) / 128);
    gemm_tc<<<gPred, 256>>>(feat_s, H3, lin_sub_w, H3, lin_sub_b,
                            out + 1 + (size_t)BE, Ee, Bq, Ee, H3);   // ob_pred
    gemm_tc<<<gPred, 256>>>(feat_o, H3, lin_ob_w, H3, lin_ob_b,
                            out + 1, Ee, Bq, Ee, H3);                // sub_pred

    // 9) CE log-probs + finalize (deterministic fixed-order sum)
    ce_kernel<<<Bq, 256>>>(out + 1 + (size_t)BE, trip, sidx, 2, lp0); // ob_pred vs o[s_idx]
    ce_kernel<<<Bq, 256>>>(out + 1,              trip, oidx, 0, lp1); // sub_pred vs s[o_idx]
    finalize_kernel<<<1, 512>>>(out);
}

// round 8
// speedup vs baseline: 2.5398x; 1.0064x over previous
#include <cuda_runtime.h>
#include <math.h>
#include <stdint.h>

// Problem constants
#define Bq 512
#define Tt 10
#define Nn 50
#define Hh 200
#define Ee 10000
#define Rr 200
#define H3 600
#define BE (Bq*Ee)

// ---------------- scratch (static __device__, no allocations) ----------------
__device__ float g_proj_s[Ee*Hh];
__device__ float g_proj_o[Ee*Hh];
__device__ float g_bias_s[Bq*Hh];
__device__ float g_bias_o[Bq*Hh];
__device__ float g_seq_s[Bq*Tt*H3];
__device__ float g_seq_o[Bq*Tt*H3];
__device__ float g_gi_s[Bq*Tt*H3];
__device__ float g_gi_o[Bq*Tt*H3];
__device__ float g_h_s[Bq*Hh];
__device__ float g_h_o[Bq*Hh];
__device__ float g_feat_s[Bq*H3];
__device__ float g_feat_o[Bq*H3];
__device__ float g_lp0[Bq];
__device__ float g_lp1[Bq];
__device__ int   g_sidx[Bq];
__device__ int   g_oidx[Bq];

__device__ __forceinline__ float tanh_fast(float x) {
    float y;
    asm("tanh.approx.f32 %0, %1;" : "=f"(y) : "f"(x));
    return y;
}

__device__ __forceinline__ uint32_t cvt_tf32(float x) {
    uint32_t y;
    asm("cvt.rna.tf32.f32 %0, %1;" : "=r"(y) : "f"(x));
    return y;
}

__device__ __forceinline__ void mma_tf32(float* d, const uint32_t* a, const uint32_t* b) {
    asm volatile(
        "mma.sync.aligned.m16n8k8.row.col.f32.tf32.tf32.f32 "
        "{%0,%1,%2,%3}, {%4,%5,%6,%7}, {%8,%9}, {%0,%1,%2,%3};"
        : "+f"(d[0]), "+f"(d[1]), "+f"(d[2]), "+f"(d[3])
        : "r"(a[0]), "r"(a[1]), "r"(a[2]), "r"(a[3]), "r"(b[0]), "r"(b[1]));
}

__device__ __forceinline__ void cp16(uint32_t dst, const float* src) {
    asm volatile("cp.async.cg.shared.global [%0], [%1], 16;" :: "r"(dst), "l"(src));
}
__device__ __forceinline__ void cp_commit() {
    asm volatile("cp.async.commit_group;");
}

// ---------------- parallel stable descending argsort (rank-based) ------------
__global__ void sort_kernel(const int* __restrict__ s_hlen, const int* __restrict__ o_hlen)
{
    int t = threadIdx.x;              // 1024 threads: [0,512) -> s, [512,1024) -> o
    int b = t & 511;
    const int* L = (t < 512) ? s_hlen : o_hlen;
    int lv = L[b];
    int r = 0;
    for (int j = 0; j < Bq; j++) {
        int v = L[j];
        r += (v > lv) || (v == lv && j < b);
    }
    if (t < 512) g_sidx[r] = b; else g_oidx[r] = b;
}

// ============ tf32 tensor-core GEMM v3: C[M,N] = A[M,K] @ W[N,K]^T (+bias) ===
// CTA tile 128x64, 8 warps (4m x 2n), warp tile 32x32 = 2x4 m16n8k8.
// cp.async 16B staging (raw fp32), 3-stage pipeline; cvt.rna.tf32 applied to
// FRAGMENTS in registers (restores round-to-nearest numerics of R6).
// 16B-chunk XOR swizzle (c ^ ((row>>2)&1)) -> conflict-free fragment LDS.
// Requires K % 8 == 0, A/W rows 16B-aligned, K >= 16. Scalar C stores.
__global__ __launch_bounds__(256)
void gemm_tc(const float* __restrict__ A, int lda,
             const float* __restrict__ W, int ldw,
             const float* __restrict__ bias,
             float* __restrict__ C, int ldc,
             int M, int N, int K)
{
    __shared__ float As[3][128][8];
    __shared__ float Ws[3][64][8];

    const int tid  = threadIdx.x;
    const int bm   = blockIdx.y * 128;
    const int bn   = blockIdx.x * 64;
    const int wid  = tid >> 5, lane = tid & 31;
    const int gid  = lane >> 2, tig = lane & 3;
    const int wm   = (wid & 3) * 32;
    const int wn   = (wid >> 2) * 32;

    // ---- staging setup (per-thread constant) ----
    const int sm_r = tid >> 1;                 // A row in tile (0..127)
    const int sc   = tid & 1;                  // 16B chunk (0/1)
    uint32_t aDst = (uint32_t)__cvta_generic_to_shared(
        &As[0][sm_r][4 * (sc ^ ((sm_r >> 2) & 1))]);
    int rA = bm + sm_r; if (rA > M - 1) rA = M - 1;
    const float* aSrc = A + (size_t)rA * lda + 4 * sc;

    uint32_t wDst = 0; const float* wSrc = A;  // dummy init
    const bool doW = (tid < 128);
    if (doW) {
        const int sn = tid >> 1;               // W row in tile (0..63)
        wDst = (uint32_t)__cvta_generic_to_shared(
            &Ws[0][sn][4 * (sc ^ ((sn >> 2) & 1))]);
        int rW = bn + sn; if (rW > N - 1) rW = N - 1;
        wSrc = W + (size_t)rW * ldw + 4 * sc;
    }
    const uint32_t A_ST = 128 * 8 * 4;         // bytes per A stage
    const uint32_t W_ST = 64 * 8 * 4;

    const int nt = K >> 3;

    // prologue: stage 0 and 1
    cp16(aDst, aSrc);
    if (doW) cp16(wDst, wSrc);
    cp_commit();
    cp16(aDst + A_ST, aSrc + 8);
    if (doW) cp16(wDst + W_ST, wSrc + 8);
    cp_commit();

    float acc[2][4][4];
#pragma unroll
    for (int i = 0; i < 2; i++)
#pragma unroll
        for (int j = 0; j < 4; j++)
#pragma unroll
            for (int e = 0; e < 4; e++) acc[i][j][e] = 0.f;

    // fragment swizzle: s = gid>>2 ((mb>>2)&1 == (nb>>2)&1 == gid>>2)
    const int s   = gid >> 2;
    const int klo = 4 * s + tig;          // k = tig
    const int khi = 4 - 4 * s + tig;      // k = tig + 4

    int buf = 0;
    for (int kt = 0; kt < nt; kt++) {
        if (kt < nt - 1) asm volatile("cp.async.wait_group 1;");
        else             asm volatile("cp.async.wait_group 0;");
        __syncthreads();

        // stage kt+2 into slot (buf+2)%3
        if (kt + 2 < nt) {
            int slot = buf + 2; if (slot >= 3) slot -= 3;
            int k0 = (kt + 2) << 3;
            cp16(aDst + (uint32_t)slot * A_ST, aSrc + k0);
            if (doW) cp16(wDst + (uint32_t)slot * W_ST, wSrc + k0);
            cp_commit();
        }

        // fragments (conflict-free LDS) + cvt.rna.tf32 in registers
        uint32_t afr[2][4], bfr[4][2];
#pragma unroll
        for (int i = 0; i < 2; i++) {
            int mb = wm + 16 * i + gid;
            afr[i][0] = cvt_tf32(As[buf][mb    ][klo]);
            afr[i][1] = cvt_tf32(As[buf][mb + 8][klo]);
            afr[i][2] = cvt_tf32(As[buf][mb    ][khi]);
            afr[i][3] = cvt_tf32(As[buf][mb + 8][khi]);
        }
#pragma unroll
        for (int j = 0; j < 4; j++) {
            int nb = wn + 8 * j + gid;
            bfr[j][0] = cvt_tf32(Ws[buf][nb][klo]);
            bfr[j][1] = cvt_tf32(Ws[buf][nb][khi]);
        }
#pragma unroll
        for (int i = 0; i < 2; i++)
#pragma unroll
            for (int j = 0; j < 4; j++)
                mma_tf32(acc[i][j], afr[i], bfr[j]);

        buf++; if (buf >= 3) buf = 0;
    }

    // epilogue (scalar stores — C may be misaligned, e.g. d_out+1)
#pragma unroll
    for (int i = 0; i < 2; i++) {
        int r0 = bm + wm + 16 * i + gid;
        int r1 = r0 + 8;
#pragma unroll
        for (int j = 0; j < 4; j++) {
            int c = bn + wn + 8 * j + 2 * tig;
            if (c < N) {   // N even in all calls -> c+1 < N too
                float b0 = bias ? bias[c]     : 0.f;
                float b1 = bias ? bias[c + 1] : 0.f;
                if (r0 < M) {
                    C[(size_t)r0 * ldc + c]     = acc[i][j][0] + b0;
                    C[(size_t)r0 * ldc + c + 1] = acc[i][j][1] + b1;
                }
                if (r1 < M) {
                    C[(size_t)r1 * ldc + c]     = acc[i][j][2] + b0;
                    C[(size_t)r1 * ldc + c + 1] = acc[i][j][3] + b1;
                }
            }
        }
    }
}

// ---------------- fused GRU: whole T-loop in one launch -----------------------
// grid (64, 2): x = batch-block of 8, y = stream (0=s, 1=o). 256 threads.
__global__ __launch_bounds__(256)
void gru_fused(const float* __restrict__ Whh_s, const float* __restrict__ bhh_s,
               const float* __restrict__ Whh_o, const float* __restrict__ bhh_o,
               const int* __restrict__ slen, const int* __restrict__ olen)
{
    const int z = blockIdx.y;
    const float* Whh = z ? Whh_o : Whh_s;
    const float* bhh = z ? bhh_o : bhh_s;
    const float* gi  = z ? g_gi_o : g_gi_s;
    float* hout      = z ? g_h_o : g_h_s;
    const int* len   = z ? olen : slen;
    const int b0 = blockIdx.x * 8;
    const int tid = threadIdx.x;

    __shared__ float h_sm[8][Hh];      // 6.4 KB
    __shared__ float gh_sm[8][H3];     // 19.2 KB
    __shared__ int   len_sm[8];

    for (int i = tid; i < 8 * Hh; i += 256) h_sm[i / Hh][i % Hh] = 0.f;
    if (tid < 8) len_sm[tid] = len[b0 + tid];
    __syncthreads();

    for (int t = 0; t < Tt; t++) {
        // gh = h @ Whh^T + bhh
        for (int j = tid; j < H3; j += 256) {
            const float* wrow = Whh + (size_t)j * Hh;
            float acc[8];
#pragma unroll
            for (int b = 0; b < 8; b++) acc[b] = 0.f;
            for (int k = 0; k < Hh; k += 4) {
                float4 w = *(const float4*)(wrow + k);
#pragma unroll
                for (int b = 0; b < 8; b++) {
                    float4 h4 = *(const float4*)&h_sm[b][k];
                    acc[b] += w.x * h4.x + w.y * h4.y + w.z * h4.z + w.w * h4.w;
                }
            }
            float bb = bhh[j];
#pragma unroll
            for (int b = 0; b < 8; b++) gh_sm[b][j] = acc[b] + bb;
        }
        __syncthreads();

        // gate update
        for (int idx = tid; idx < 8 * Hh; idx += 256) {
            int b = idx / Hh, jj = idx % Hh;
            if (t < len_sm[b]) {
                const float* gib = gi + ((size_t)(b0 + b) * Tt + t) * H3;
                float ir = gib[jj], iz = gib[Hh + jj], in = gib[2 * Hh + jj];
                float hr = gh_sm[b][jj], hz = gh_sm[b][Hh + jj], hn = gh_sm[b][2 * Hh + jj];
                float rg = 1.f / (1.f + expf(-(ir + hr)));
                float zg = 1.f / (1.f + expf(-(iz + hz)));
                float ng = tanhf(in + rg * hn);
                h_sm[b][jj] = (1.f - zg) * ng + zg * h_sm[b][jj];
            }
        }
        __syncthreads();
    }

    for (int i = tid; i < 8 * Hh; i += 256)
        hout[(size_t)(b0 + i / Hh) * Hh + (i % Hh)] = h_sm[i / Hh][i % Hh];
}

// ---------------- per-batch attention bias: ba + se@Ws^T + re@Wr^T -----------
__global__ void bias_kernel(const int* __restrict__ trip, int scol,
                            const float* __restrict__ ent,
                            const float* __restrict__ Wa,  // (H, 3H) row-major
                            const float* __restrict__ ba,
                            float* __restrict__ bias)
{
    int b = blockIdx.x;
    __shared__ float se[Hh], re[Hh];
    int tid = threadIdx.x;
    int sid = trip[b * 3 + scol], rid = trip[b * 3 + 1];
    for (int h = tid; h < Hh; h += 256) {
        se[h] = ent[(size_t)sid * Hh + h];
        re[h] = ent[(size_t)rid * Hh + h];
    }
    __syncthreads();
    for (int g = tid; g < Hh; g += 256) {
        const float* wrow = Wa + (size_t)g * H3;
        float acc = ba[g];
#pragma unroll 4
        for (int h = 0; h < Hh; h++)
            acc += se[h] * wrow[Hh + h] + re[h] * wrow[2 * Hh + h];
        bias[b * Hh + g] = acc;
    }
}

// ---------------- attention + softmax + weighted sum + seq assembly ----------
__global__ void attn_kernel(const int* __restrict__ neigh, const int* __restrict__ nlen,
                            const int* __restrict__ hlen, const int* __restrict__ trip,
                            int scol,
                            const float* __restrict__ ent, const float* __restrict__ rel,
                            const float* __restrict__ proj, const float* __restrict__ bias,
                            const float* __restrict__ v, float* __restrict__ seq)
{
    const int bt = blockIdx.x;
    const int b = bt / Tt, t = bt % Tt;
    __shared__ float s_bias[Hh], s_v[Hh];
    __shared__ float s_logit[Nn], s_w[Nn];
    __shared__ int s_nidx[Nn];
    const int tid = threadIdx.x;
    for (int g = tid; g < Hh; g += 256) { s_bias[g] = bias[b * Hh + g]; s_v[g] = v[g]; }
    for (int n = tid; n < Nn; n += 256) s_nidx[n] = neigh[((size_t)b * Tt + t) * Nn + n];
    __syncthreads();
    const int nl = nlen[b * Tt + t];
    const int warp = tid >> 5, lane = tid & 31;
    for (int n = warp; n < nl; n += 8) {
        const float* pr = proj + (size_t)s_nidx[n] * Hh;
        float acc = 0.f;
        for (int g = lane; g < Hh; g += 32)
            acc += tanh_fast(pr[g] + s_bias[g]) * s_v[g];
        for (int o = 16; o; o >>= 1) acc += __shfl_xor_sync(0xffffffffu, acc, o);
        if (lane == 0) s_logit[n] = acc;
    }
    __syncthreads();
    if (warp == 0) {
        float m = -3.4e38f;
        for (int n = lane; n < nl; n += 32) m = fmaxf(m, s_logit[n]);
        for (int o = 16; o; o >>= 1) m = fmaxf(m, __shfl_xor_sync(0xffffffffu, m, o));
        float s = 0.f;
        for (int n = lane; n < nl; n += 32) { float e = expf(s_logit[n] - m); s_w[n] = e; s += e; }
        for (int o = 16; o; o >>= 1) s += __shfl_xor_sync(0xffffffffu, s, o);
        float inv = 1.f / s;
        for (int n = lane; n < nl; n += 32) s_w[n] *= inv;
    }
    __syncthreads();
    const float msk = (t < hlen[b]) ? 1.f : 0.f;
    const int sid = trip[b * 3 + scol], rid = trip[b * 3 + 1];
    float* out = seq + ((size_t)b * Tt + t) * H3;
    for (int h = tid; h < Hh; h += 256) {
        float acc = 0.f;
        for (int n = 0; n < nl; n++) acc += s_w[n] * ent[(size_t)s_nidx[n] * Hh + h];
        out[h] = acc * msk;
        out[Hh + h] = ent[(size_t)sid * Hh + h] * msk;
        out[2 * Hh + h] = rel[(size_t)rid * Hh + h] * msk;
    }
}

// ---------------- final feature assembly (permuted by idx) -------------------
__global__ void feat_kernel(const int* __restrict__ trip, const int* __restrict__ idx,
                            int scol, const float* __restrict__ ent,
                            const float* __restrict__ rel, const float* __restrict__ h,
                            float* __restrict__ feat)
{
    int b = blockIdx.x;
    int p = idx[b];
    int sid = trip[p * 3 + scol], rid = trip[p * 3 + 1];
    for (int i = threadIdx.x; i < Hh; i += 256) {
        feat[(size_t)b * H3 + i]          = ent[(size_t)sid * Hh + i];
        feat[(size_t)b * H3 + Hh + i]     = h[(size_t)p * Hh + i];
        feat[(size_t)b * H3 + 2*Hh + i]   = rel[(size_t)rid * Hh + i];
    }
}

// ---------------- cross-entropy per-row log-prob of label --------------------
__global__ void ce_kernel(const float* __restrict__ pred, const int* __restrict__ trip,
                          const int* __restrict__ idx, int labcol, float* __restrict__ lp)
{
    int b = blockIdx.x;
    const float* row = pred + (size_t)b * Ee;
    int tid = threadIdx.x;
    int lane = tid & 31, warp = tid >> 5;
    __shared__ float sred[8];

    float m = -3.4e38f;
    for (int i = tid; i < Ee; i += 256) m = fmaxf(m, row[i]);
    for (int o = 16; o; o >>= 1) m = fmaxf(m, __shfl_xor_sync(0xffffffffu, m, o));
    if (lane == 0) sred[warp] = m;
    __syncthreads();
    if (tid == 0) {
        float mm = sred[0];
        for (int i = 1; i < 8; i++) mm = fmaxf(mm, sred[i]);
        sred[0] = mm;
    }
    __syncthreads();
    m = sred[0];
    __syncthreads();

    float s = 0.f;
    for (int i = tid; i < Ee; i += 256) s += expf(row[i] - m);
    for (int o = 16; o; o >>= 1) s += __shfl_xor_sync(0xffffffffu, s, o);
    if (lane == 0) sred[warp] = s;
    __syncthreads();
    if (tid == 0) {
        float st = 0.f;
        for (int i = 0; i < 8; i++) st += sred[i];
        int lab = trip[idx[b] * 3 + labcol];
        lp[b] = row[lab] - m - logf(st);
    }
}

// ---------------- finalize: loss + index outputs ------------------------------
__global__ void finalize_kernel(float* __restrict__ out)
{
    int tid = threadIdx.x;
    if (tid == 0) {
        double a = 0.0, c = 0.0;
        for (int b = 0; b < Bq; b++) { a += (double)g_lp0[b]; c += (double)g_lp1[b]; }
        out[0] = (float)(-(a / (double)Bq) - (c / (double)Bq));
    }
    for (int b = tid; b < Bq; b += blockDim.x) {
        out[1 + 2 * (size_t)BE + b]       = (float)g_oidx[b];
        out[1 + 2 * (size_t)BE + Bq + b]  = (float)g_sidx[b];
    }
}

// ---------------- host-side orchestration ------------------------------------
extern "C" void kernel_launch(void* const* d_in, const int* in_sizes, int n_in,
                              void* d_out, int out_size)
{
    const int*   trip     = (const int*)d_in[0];
    const int*   s_neigh  = (const int*)d_in[1];
    const int*   s_nlen   = (const int*)d_in[2];
    const int*   s_hlen   = (const int*)d_in[3];
    const int*   o_neigh  = (const int*)d_in[4];
    const int*   o_nlen   = (const int*)d_in[5];
    const int*   o_hlen   = (const int*)d_in[6];
    const float* ent      = (const float*)d_in[7];
    const float* rel      = (const float*)d_in[8];
    const float* attn_s_w = (const float*)d_in[9];
    const float* attn_s_b = (const float*)d_in[10];
    const float* v_s      = (const float*)d_in[11];
    const float* attn_o_w = (const float*)d_in[12];
    const float* attn_o_b = (const float*)d_in[13];
    const float* v_o      = (const float*)d_in[14];
    const float* sub_w_ih = (const float*)d_in[15];
    const float* sub_w_hh = (const float*)d_in[16];
    const float* sub_b_ih = (const float*)d_in[17];
    const float* sub_b_hh = (const float*)d_in[18];
    const float* ob_w_ih  = (const float*)d_in[19];
    const float* ob_w_hh  = (const float*)d_in[20];
    const float* ob_b_ih  = (const float*)d_in[21];
    const float* ob_b_hh  = (const float*)d_in[22];
    const float* lin_sub_w = (const float*)d_in[23];
    const float* lin_sub_b = (const float*)d_in[24];
    const float* lin_ob_w  = (const float*)d_in[25];
    const float* lin_ob_b  = (const float*)d_in[26];
    float* out = (float*)d_out;

    float *proj_s, *proj_o, *bias_s, *bias_o, *seq_s, *seq_o, *gi_s, *gi_o;
    float *h_s, *h_o, *feat_s, *feat_o, *lp0, *lp1;
    int *sidx, *oidx;
    cudaGetSymbolAddress((void**)&proj_s, g_proj_s);
    cudaGetSymbolAddress((void**)&proj_o, g_proj_o);
    cudaGetSymbolAddress((void**)&bias_s, g_bias_s);
    cudaGetSymbolAddress((void**)&bias_o, g_bias_o);
    cudaGetSymbolAddress((void**)&seq_s,  g_seq_s);
    cudaGetSymbolAddress((void**)&seq_o,  g_seq_o);
    cudaGetSymbolAddress((void**)&gi_s,   g_gi_s);
    cudaGetSymbolAddress((void**)&gi_o,   g_gi_o);
    cudaGetSymbolAddress((void**)&h_s,    g_h_s);
    cudaGetSymbolAddress((void**)&h_o,    g_h_o);
    cudaGetSymbolAddress((void**)&feat_s, g_feat_s);
    cudaGetSymbolAddress((void**)&feat_o, g_feat_o);
    cudaGetSymbolAddress((void**)&lp0,    g_lp0);
    cudaGetSymbolAddress((void**)&lp1,    g_lp1);
    cudaGetSymbolAddress((void**)&sidx,   g_sidx);
    cudaGetSymbolAddress((void**)&oidx,   g_oidx);

    // 1) parallel stable descending argsort
    sort_kernel<<<1, 1024>>>(s_hlen, o_hlen);

    // 2) entity projections through Wn (attn weight cols [0:H))  M=Ee,N=Hh,K=Hh
    dim3 gProj((Hh + 63) / 64, (Ee + 127) / 128);
    gemm_tc<<<gProj, 256>>>(ent, Hh, attn_s_w, H3, nullptr, proj_s, Hh, Ee, Hh, Hh);
    gemm_tc<<<gProj, 256>>>(ent, Hh, attn_o_w, H3, nullptr, proj_o, Hh, Ee, Hh, Hh);

    // 3) per-batch bias terms (se@Ws^T + re@Wr^T + ba)
    bias_kernel<<<Bq, 256>>>(trip, 0, ent, attn_s_w, attn_s_b, bias_s);
    bias_kernel<<<Bq, 256>>>(trip, 2, ent, attn_o_w, attn_o_b, bias_o);

    // 4) attention + softmax + weighted neighbor sum + seq assembly
    attn_kernel<<<Bq * Tt, 256>>>(s_neigh, s_nlen, s_hlen, trip, 0, ent, rel,
                                  proj_s, bias_s, v_s, seq_s);
    attn_kernel<<<Bq * Tt, 256>>>(o_neigh, o_nlen, o_hlen, trip, 2, ent, rel,
                                  proj_o, bias_o, v_o, seq_o);

    // 5) GRU input gates for all timesteps at once (M=B*T, N=3H, K=3H)
    dim3 gGi((H3 + 63) / 64, (Bq * Tt + 127) / 128);
    gemm_tc<<<gGi, 256>>>(seq_s, H3, sub_w_ih, H3, sub_b_ih, gi_s, H3, Bq * Tt, H3, H3);
    gemm_tc<<<gGi, 256>>>(seq_o, H3, ob_w_ih,  H3, ob_b_ih,  gi_o, H3, Bq * Tt, H3, H3);

    // 6) fused GRU — whole T-loop, both streams, one launch
    gru_fused<<<dim3(Bq / 8, 2), 256>>>(sub_w_hh, sub_b_hh, ob_w_hh, ob_b_hh,
                                        s_hlen, o_hlen);

    // 7) permuted feature assembly
    feat_kernel<<<Bq, 256>>>(trip, sidx, 0, ent, rel, h_s, feat_s);
    feat_kernel<<<Bq, 256>>>(trip, oidx, 2, ent, rel, h_o, feat_o);

    // 8) prediction GEMMs directly into d_out (M=Bq, N=Ee, K=3H)
    //    layout: [loss(1) | sub_pred(B*E) | ob_pred(B*E) | o_idx(B) | s_idx(B)]
    dim3 gPred((Ee + 63) / 64, (Bq + 127) / 128);
    gemm_tc<<<gPred, 256>>>(feat_s, H3, lin_sub_w, H3, lin_sub_b,
                            out + 1 + (size_t)BE, Ee, Bq, Ee, H3);   // ob_pred
    gemm_tc<<<gPred, 256>>>(feat_o, H3, lin_ob_w, H3, lin_ob_b,
                            out + 1, Ee, Bq, Ee, H3);                // sub_pred

    // 9) CE log-probs + finalize (deterministic fixed-order sum)
    ce_kernel<<<Bq, 256>>>(out + 1 + (size_t)BE, trip, sidx, 2, lp0); // ob_pred vs o[s_idx]
    ce_kernel<<<Bq, 256>>>(out + 1,              trip, oidx, 0, lp1); // sub_pred vs s[o_idx]
    finalize_kernel<<<1, 512>>>(out);
}

// round 9
// speedup vs baseline: 3.0399x; 1.1969x over previous
#include <cuda_runtime.h>
#include <math.h>
#include <stdint.h>

// Problem constants
#define Bq 512
#define Tt 10
#define Nn 50
#define Hh 200
#define Ee 10000
#define Rr 200
#define H3 600
#define H2 400
#define BE (Bq*Ee)

// ---------------- scratch (static __device__, no allocations) ----------------
__device__ float g_proj_s[Ee*Hh];
__device__ float g_proj_o[Ee*Hh];
__device__ float g_x_s[Bq*H2];
__device__ float g_x_o[Bq*H2];
__device__ float g_bias_s[Bq*Hh];
__device__ float g_bias_o[Bq*Hh];
__device__ float g_seq_s[Bq*Tt*H3];
__device__ float g_seq_o[Bq*Tt*H3];
__device__ float g_gi_s[Bq*Tt*H3];
__device__ float g_gi_o[Bq*Tt*H3];
__device__ float g_h_s[Bq*Hh];
__device__ float g_h_o[Bq*Hh];
__device__ float g_feat_s[Bq*H3];
__device__ float g_feat_o[Bq*H3];
__device__ float g_lp0[Bq];
__device__ float g_lp1[Bq];
__device__ int   g_sidx[Bq];
__device__ int   g_oidx[Bq];

__device__ __forceinline__ float tanh_fast(float x) {
    float y;
    asm("tanh.approx.f32 %0, %1;" : "=f"(y) : "f"(x));
    return y;
}

__device__ __forceinline__ uint32_t cvt_tf32(float x) {
    uint32_t y;
    asm("cvt.rna.tf32.f32 %0, %1;" : "=r"(y) : "f"(x));
    return y;
}

__device__ __forceinline__ void mma_tf32(float* d, const uint32_t* a, const uint32_t* b) {
    asm volatile(
        "mma.sync.aligned.m16n8k8.row.col.f32.tf32.tf32.f32 "
        "{%0,%1,%2,%3}, {%4,%5,%6,%7}, {%8,%9}, {%0,%1,%2,%3};"
        : "+f"(d[0]), "+f"(d[1]), "+f"(d[2]), "+f"(d[3])
        : "r"(a[0]), "r"(a[1]), "r"(a[2]), "r"(a[3]), "r"(b[0]), "r"(b[1]));
}

__device__ __forceinline__ void cp16(uint32_t dst, const float* src) {
    asm volatile("cp.async.cg.shared.global [%0], [%1], 16;" :: "r"(dst), "l"(src));
}
__device__ __forceinline__ void cp_commit() {
    asm volatile("cp.async.commit_group;");
}

// ---------------- parallel stable descending argsort (rank-based) ------------
__global__ void sort_kernel(const int* __restrict__ s_hlen, const int* __restrict__ o_hlen)
{
    __shared__ int sv[Bq], ov[Bq];
    int t = threadIdx.x;              // 1024 threads: [0,512) -> s, [512,1024) -> o
    int b = t & 511;
    if (t < 512) sv[b] = s_hlen[b]; else ov[b] = o_hlen[b];
    __syncthreads();
    const int* L = (t < 512) ? sv : ov;
    int lv = L[b];
    int r = 0;
    for (int j = 0; j < Bq; j++) {
        int v = L[j];
        r += (v > lv) || (v == lv && j < b);
    }
    if (t < 512) g_sidx[r] = b; else g_oidx[r] = b;
}

// ============ tf32 tensor-core GEMM: C[M,N] = A[M,K] @ W[N,K]^T (+bias) ======
// CTA tile 128x64, 8 warps (4m x 2n), warp tile 32x32 = 2x4 m16n8k8.
// cp.async 16B staging, 3-stage pipeline; cvt.rna.tf32 on fragments in regs.
// 16B-chunk XOR swizzle -> conflict-free fragment LDS.
// Requires K % 8 == 0, A/W rows 16B-aligned, K >= 16. Scalar C stores.
__device__ __forceinline__
void gemm_tc_body(const float* __restrict__ A, int lda,
                  const float* __restrict__ W, int ldw,
                  const float* __restrict__ bias,
                  float* __restrict__ C, int ldc,
                  int M, int N, int K)
{
    __shared__ float As[3][128][8];
    __shared__ float Ws[3][64][8];

    const int tid  = threadIdx.x;
    const int bm   = blockIdx.y * 128;
    const int bn   = blockIdx.x * 64;
    const int wid  = tid >> 5, lane = tid & 31;
    const int gid  = lane >> 2, tig = lane & 3;
    const int wm   = (wid & 3) * 32;
    const int wn   = (wid >> 2) * 32;

    // ---- staging setup ----
    const int sm_r = tid >> 1;
    const int sc   = tid & 1;
    uint32_t aDst = (uint32_t)__cvta_generic_to_shared(
        &As[0][sm_r][4 * (sc ^ ((sm_r >> 2) & 1))]);
    int rA = bm + sm_r; if (rA > M - 1) rA = M - 1;
    const float* aSrc = A + (size_t)rA * lda + 4 * sc;

    uint32_t wDst = 0; const float* wSrc = A;
    const bool doW = (tid < 128);
    if (doW) {
        const int sn = tid >> 1;
        wDst = (uint32_t)__cvta_generic_to_shared(
            &Ws[0][sn][4 * (sc ^ ((sn >> 2) & 1))]);
        int rW = bn + sn; if (rW > N - 1) rW = N - 1;
        wSrc = W + (size_t)rW * ldw + 4 * sc;
    }
    const uint32_t A_ST = 128 * 8 * 4;
    const uint32_t W_ST = 64 * 8 * 4;

    const int nt = K >> 3;

    cp16(aDst, aSrc);
    if (doW) cp16(wDst, wSrc);
    cp_commit();
    cp16(aDst + A_ST, aSrc + 8);
    if (doW) cp16(wDst + W_ST, wSrc + 8);
    cp_commit();

    float acc[2][4][4];
#pragma unroll
    for (int i = 0; i < 2; i++)
#pragma unroll
        for (int j = 0; j < 4; j++)
#pragma unroll
            for (int e = 0; e < 4; e++) acc[i][j][e] = 0.f;

    const int s   = gid >> 2;
    const int klo = 4 * s + tig;
    const int khi = 4 - 4 * s + tig;

    int buf = 0;
    for (int kt = 0; kt < nt; kt++) {
        if (kt < nt - 1) asm volatile("cp.async.wait_group 1;");
        else             asm volatile("cp.async.wait_group 0;");
        __syncthreads();

        if (kt + 2 < nt) {
            int slot = buf + 2; if (slot >= 3) slot -= 3;
            int k0 = (kt + 2) << 3;
            cp16(aDst + (uint32_t)slot * A_ST, aSrc + k0);
            if (doW) cp16(wDst + (uint32_t)slot * W_ST, wSrc + k0);
            cp_commit();
        }

        uint32_t afr[2][4], bfr[4][2];
#pragma unroll
        for (int i = 0; i < 2; i++) {
            int mb = wm + 16 * i + gid;
            afr[i][0] = cvt_tf32(As[buf][mb    ][klo]);
            afr[i][1] = cvt_tf32(As[buf][mb + 8][klo]);
            afr[i][2] = cvt_tf32(As[buf][mb    ][khi]);
            afr[i][3] = cvt_tf32(As[buf][mb + 8][khi]);
        }
#pragma unroll
        for (int j = 0; j < 4; j++) {
            int nb = wn + 8 * j + gid;
            bfr[j][0] = cvt_tf32(Ws[buf][nb][klo]);
            bfr[j][1] = cvt_tf32(Ws[buf][nb][khi]);
        }
#pragma unroll
        for (int i = 0; i < 2; i++)
#pragma unroll
            for (int j = 0; j < 4; j++)
                mma_tf32(acc[i][j], afr[i], bfr[j]);

        buf++; if (buf >= 3) buf = 0;
    }

    // epilogue (scalar stores — C may be misaligned, e.g. d_out+1)
#pragma unroll
    for (int i = 0; i < 2; i++) {
        int r0 = bm + wm + 16 * i + gid;
        int r1 = r0 + 8;
#pragma unroll
        for (int j = 0; j < 4; j++) {
            int c = bn + wn + 8 * j + 2 * tig;
            if (c < N) {
                float b0 = bias ? bias[c]     : 0.f;
                float b1 = bias ? bias[c + 1] : 0.f;
                if (r0 < M) {
                    C[(size_t)r0 * ldc + c]     = acc[i][j][0] + b0;
                    C[(size_t)r0 * ldc + c + 1] = acc[i][j][1] + b1;
                }
                if (r1 < M) {
                    C[(size_t)r1 * ldc + c]     = acc[i][j][2] + b0;
                    C[(size_t)r1 * ldc + c + 1] = acc[i][j][3] + b1;
                }
            }
        }
    }
}

// dual-gemm: blockIdx.z selects between two identical-shape GEMMs (s/o pair)
struct GemmArgs {
    const float* A; int lda;
    const float* W; int ldw;
    const float* bias;
    float* C; int ldc;
};

__global__ __launch_bounds__(256)
void gemm_tc_dual(GemmArgs a0, GemmArgs a1, int M, int N, int K)
{
    const GemmArgs& g = blockIdx.z ? a1 : a0;
    gemm_tc_body(g.A, g.lda, g.W, g.ldw, g.bias, g.C, g.ldc, M, N, K);
}

// ---------------- gather X = [ent[sid] || ent[rid]] for bias GEMM ------------
__global__ void gather_x(const int* __restrict__ trip, const float* __restrict__ ent)
{
    int b = blockIdx.x, z = blockIdx.y;
    float* X = (z ? g_x_o : g_x_s) + (size_t)b * H2;
    int scol = z ? 2 : 0;
    int sid = trip[b * 3 + scol], rid = trip[b * 3 + 1];
    for (int i = threadIdx.x; i < Hh; i += 128) {
        X[i]      = ent[(size_t)sid * Hh + i];
        X[Hh + i] = ent[(size_t)rid * Hh + i];
    }
}

// ---------------- fused GRU: whole T-loop in one launch -----------------------
__global__ __launch_bounds__(256)
void gru_fused(const float* __restrict__ Whh_s, const float* __restrict__ bhh_s,
               const float* __restrict__ Whh_o, const float* __restrict__ bhh_o,
               const int* __restrict__ slen, const int* __restrict__ olen)
{
    const int z = blockIdx.y;
    const float* Whh = z ? Whh_o : Whh_s;
    const float* bhh = z ? bhh_o : bhh_s;
    const float* gi  = z ? g_gi_o : g_gi_s;
    float* hout      = z ? g_h_o : g_h_s;
    const int* len   = z ? olen : slen;
    const int b0 = blockIdx.x * 8;
    const int tid = threadIdx.x;

    __shared__ float h_sm[8][Hh];
    __shared__ float gh_sm[8][H3];
    __shared__ int   len_sm[8];

    for (int i = tid; i < 8 * Hh; i += 256) h_sm[i / Hh][i % Hh] = 0.f;
    if (tid < 8) len_sm[tid] = len[b0 + tid];
    __syncthreads();

    for (int t = 0; t < Tt; t++) {
        for (int j = tid; j < H3; j += 256) {
            const float* wrow = Whh + (size_t)j * Hh;
            float acc[8];
#pragma unroll
            for (int b = 0; b < 8; b++) acc[b] = 0.f;
            for (int k = 0; k < Hh; k += 4) {
                float4 w = *(const float4*)(wrow + k);
#pragma unroll
                for (int b = 0; b < 8; b++) {
                    float4 h4 = *(const float4*)&h_sm[b][k];
                    acc[b] += w.x * h4.x + w.y * h4.y + w.z * h4.z + w.w * h4.w;
                }
            }
            float bb = bhh[j];
#pragma unroll
            for (int b = 0; b < 8; b++) gh_sm[b][j] = acc[b] + bb;
        }
        __syncthreads();

        for (int idx = tid; idx < 8 * Hh; idx += 256) {
            int b = idx / Hh, jj = idx % Hh;
            if (t < len_sm[b]) {
                const float* gib = gi + ((size_t)(b0 + b) * Tt + t) * H3;
                float ir = gib[jj], iz = gib[Hh + jj], in = gib[2 * Hh + jj];
                float hr = gh_sm[b][jj], hz = gh_sm[b][Hh + jj], hn = gh_sm[b][2 * Hh + jj];
                float rg = 1.f / (1.f + expf(-(ir + hr)));
                float zg = 1.f / (1.f + expf(-(iz + hz)));
                float ng = tanhf(in + rg * hn);
                h_sm[b][jj] = (1.f - zg) * ng + zg * h_sm[b][jj];
            }
        }
        __syncthreads();
    }

    for (int i = tid; i < 8 * Hh; i += 256)
        hout[(size_t)(b0 + i / Hh) * Hh + (i % Hh)] = h_sm[i / Hh][i % Hh];
}

// ---------------- attention + softmax + weighted sum + seq assembly ----------
__global__ void attn_kernel(const int* __restrict__ neigh, const int* __restrict__ nlen,
                            const int* __restrict__ hlen, const int* __restrict__ trip,
                            int scol,
                            const float* __restrict__ ent, const float* __restrict__ rel,
                            const float* __restrict__ proj, const float* __restrict__ bias,
                            const float* __restrict__ v, float* __restrict__ seq)
{
    const int bt = blockIdx.x;
    const int b = bt / Tt, t = bt % Tt;
    __shared__ float s_bias[Hh], s_v[Hh];
    __shared__ float s_logit[Nn], s_w[Nn];
    __shared__ int s_nidx[Nn];
    const int tid = threadIdx.x;
    for (int g = tid; g < Hh; g += 256) { s_bias[g] = bias[b * Hh + g]; s_v[g] = v[g]; }
    for (int n = tid; n < Nn; n += 256) s_nidx[n] = neigh[((size_t)b * Tt + t) * Nn + n];
    __syncthreads();
    const int nl = nlen[b * Tt + t];
    const int warp = tid >> 5, lane = tid & 31;
    for (int n = warp; n < nl; n += 8) {
        const float* pr = proj + (size_t)s_nidx[n] * Hh;
        float acc = 0.f;
        for (int g = lane; g < Hh; g += 32)
            acc += tanh_fast(pr[g] + s_bias[g]) * s_v[g];
        for (int o = 16; o; o >>= 1) acc += __shfl_xor_sync(0xffffffffu, acc, o);
        if (lane == 0) s_logit[n] = acc;
    }
    __syncthreads();
    if (warp == 0) {
        float m = -3.4e38f;
        for (int n = lane; n < nl; n += 32) m = fmaxf(m, s_logit[n]);
        for (int o = 16; o; o >>= 1) m = fmaxf(m, __shfl_xor_sync(0xffffffffu, m, o));
        float s = 0.f;
        for (int n = lane; n < nl; n += 32) { float e = expf(s_logit[n] - m); s_w[n] = e; s += e; }
        for (int o = 16; o; o >>= 1) s += __shfl_xor_sync(0xffffffffu, s, o);
        float inv = 1.f / s;
        for (int n = lane; n < nl; n += 32) s_w[n] *= inv;
    }
    __syncthreads();
    const float msk = (t < hlen[b]) ? 1.f : 0.f;
    const int sid = trip[b * 3 + scol], rid = trip[b * 3 + 1];
    float* out = seq + ((size_t)b * Tt + t) * H3;
    for (int h = tid; h < Hh; h += 256) {
        float acc = 0.f;
        for (int n = 0; n < nl; n++) acc += s_w[n] * ent[(size_t)s_nidx[n] * Hh + h];
        out[h] = acc * msk;
        out[Hh + h] = ent[(size_t)sid * Hh + h] * msk;
        out[2 * Hh + h] = rel[(size_t)rid * Hh + h] * msk;
    }
}

// ---------------- final feature assembly (permuted by idx) -------------------
__global__ void feat_kernel(const int* __restrict__ trip, const int* __restrict__ idx,
                            int scol, const float* __restrict__ ent,
                            const float* __restrict__ rel, const float* __restrict__ h,
                            float* __restrict__ feat)
{
    int b = blockIdx.x;
    int p = idx[b];
    int sid = trip[p * 3 + scol], rid = trip[p * 3 + 1];
    for (int i = threadIdx.x; i < Hh; i += 256) {
        feat[(size_t)b * H3 + i]          = ent[(size_t)sid * Hh + i];
        feat[(size_t)b * H3 + Hh + i]     = h[(size_t)p * Hh + i];
        feat[(size_t)b * H3 + 2*Hh + i]   = rel[(size_t)rid * Hh + i];
    }
}

// ---------------- cross-entropy per-row log-prob of label --------------------
__global__ void ce_kernel(const float* __restrict__ pred, const int* __restrict__ trip,
                          const int* __restrict__ idx, int labcol, float* __restrict__ lp)
{
    int b = blockIdx.x;
    const float* row = pred + (size_t)b * Ee;
    int tid = threadIdx.x;
    int lane = tid & 31, warp = tid >> 5;
    __shared__ float sred[8];

    float m = -3.4e38f;
    for (int i = tid; i < Ee; i += 256) m = fmaxf(m, row[i]);
    for (int o = 16; o; o >>= 1) m = fmaxf(m, __shfl_xor_sync(0xffffffffu, m, o));
    if (lane == 0) sred[warp] = m;
    __syncthreads();
    if (tid == 0) {
        float mm = sred[0];
        for (int i = 1; i < 8; i++) mm = fmaxf(mm, sred[i]);
        sred[0] = mm;
    }
    __syncthreads();
    m = sred[0];
    __syncthreads();

    float s = 0.f;
    for (int i = tid; i < Ee; i += 256) s += expf(row[i] - m);
    for (int o = 16; o; o >>= 1) s += __shfl_xor_sync(0xffffffffu, s, o);
    if (lane == 0) sred[warp] = s;
    __syncthreads();
    if (tid == 0) {
        float st = 0.f;
        for (int i = 0; i < 8; i++) st += sred[i];
        int lab = trip[idx[b] * 3 + labcol];
        lp[b] = row[lab] - m - logf(st);
    }
}

// ---------------- finalize: loss + index outputs ------------------------------
__global__ void finalize_kernel(float* __restrict__ out)
{
    int tid = threadIdx.x;
    if (tid == 0) {
        double a = 0.0, c = 0.0;
        for (int b = 0; b < Bq; b++) { a += (double)g_lp0[b]; c += (double)g_lp1[b]; }
        out[0] = (float)(-(a / (double)Bq) - (c / (double)Bq));
    }
    for (int b = tid; b < Bq; b += blockDim.x) {
        out[1 + 2 * (size_t)BE + b]       = (float)g_oidx[b];
        out[1 + 2 * (size_t)BE + Bq + b]  = (float)g_sidx[b];
    }
}

// ---------------- host-side orchestration ------------------------------------
extern "C" void kernel_launch(void* const* d_in, const int* in_sizes, int n_in,
                              void* d_out, int out_size)
{
    const int*   trip     = (const int*)d_in[0];
    const int*   s_neigh  = (const int*)d_in[1];
    const int*   s_nlen   = (const int*)d_in[2];
    const int*   s_hlen   = (const int*)d_in[3];
    const int*   o_neigh  = (const int*)d_in[4];
    const int*   o_nlen   = (const int*)d_in[5];
    const int*   o_hlen   = (const int*)d_in[6];
    const float* ent      = (const float*)d_in[7];
    const float* rel      = (const float*)d_in[8];
    const float* attn_s_w = (const float*)d_in[9];
    const float* attn_s_b = (const float*)d_in[10];
    const float* v_s      = (const float*)d_in[11];
    const float* attn_o_w = (const float*)d_in[12];
    const float* attn_o_b = (const float*)d_in[13];
    const float* v_o      = (const float*)d_in[14];
    const float* sub_w_ih = (const float*)d_in[15];
    const float* sub_w_hh = (const float*)d_in[16];
    const float* sub_b_ih = (const float*)d_in[17];
    const float* sub_b_hh = (const float*)d_in[18];
    const float* ob_w_ih  = (const float*)d_in[19];
    const float* ob_w_hh  = (const float*)d_in[20];
    const float* ob_b_ih  = (const float*)d_in[21];
    const float* ob_b_hh  = (const float*)d_in[22];
    const float* lin_sub_w = (const float*)d_in[23];
    const float* lin_sub_b = (const float*)d_in[24];
    const float* lin_ob_w  = (const float*)d_in[25];
    const float* lin_ob_b  = (const float*)d_in[26];
    float* out = (float*)d_out;

    float *proj_s, *proj_o, *x_s, *x_o, *bias_s, *bias_o, *seq_s, *seq_o;
    float *gi_s, *gi_o, *h_s, *h_o, *feat_s, *feat_o, *lp0, *lp1;
    int *sidx, *oidx;
    cudaGetSymbolAddress((void**)&proj_s, g_proj_s);
    cudaGetSymbolAddress((void**)&proj_o, g_proj_o);
    cudaGetSymbolAddress((void**)&x_s,    g_x_s);
    cudaGetSymbolAddress((void**)&x_o,    g_x_o);
    cudaGetSymbolAddress((void**)&bias_s, g_bias_s);
    cudaGetSymbolAddress((void**)&bias_o, g_bias_o);
    cudaGetSymbolAddress((void**)&seq_s,  g_seq_s);
    cudaGetSymbolAddress((void**)&seq_o,  g_seq_o);
    cudaGetSymbolAddress((void**)&gi_s,   g_gi_s);
    cudaGetSymbolAddress((void**)&gi_o,   g_gi_o);
    cudaGetSymbolAddress((void**)&h_s,    g_h_s);
    cudaGetSymbolAddress((void**)&h_o,    g_h_o);
    cudaGetSymbolAddress((void**)&feat_s, g_feat_s);
    cudaGetSymbolAddress((void**)&feat_o, g_feat_o);
    cudaGetSymbolAddress((void**)&lp0,    g_lp0);
    cudaGetSymbolAddress((void**)&lp1,    g_lp1);
    cudaGetSymbolAddress((void**)&sidx,   g_sidx);
    cudaGetSymbolAddress((void**)&oidx,   g_oidx);

    // 1) sort + X gather (independent prep)
    sort_kernel<<<1, 1024>>>(s_hlen, o_hlen);
    gather_x<<<dim3(Bq, 2), 128>>>(trip, ent);

    // 2) entity projections (both streams, one launch)  M=Ee,N=Hh,K=Hh
    {
        GemmArgs a0{ent, Hh, attn_s_w, H3, nullptr, proj_s, Hh};
        GemmArgs a1{ent, Hh, attn_o_w, H3, nullptr, proj_o, Hh};
        dim3 g((Hh + 63) / 64, (Ee + 127) / 128, 2);
        gemm_tc_dual<<<g, 256>>>(a0, a1, Ee, Hh, Hh);
    }

    // 3) bias GEMM: bias[b,g] = ba[g] + X[b,:] @ Wa[g, H:3H]^T  M=Bq,N=Hh,K=2H
    {
        GemmArgs a0{x_s, H2, attn_s_w + Hh, H3, attn_s_b, bias_s, Hh};
        GemmArgs a1{x_o, H2, attn_o_w + Hh, H3, attn_o_b, bias_o, Hh};
        dim3 g((Hh + 63) / 64, (Bq + 127) / 128, 2);
        gemm_tc_dual<<<g, 256>>>(a0, a1, Bq, Hh, H2);
    }

    // 4) attention + softmax + weighted neighbor sum + seq assembly
    attn_kernel<<<Bq * Tt, 256>>>(s_neigh, s_nlen, s_hlen, trip, 0, ent, rel,
                                  proj_s, bias_s, v_s, seq_s);
    attn_kernel<<<Bq * Tt, 256>>>(o_neigh, o_nlen, o_hlen, trip, 2, ent, rel,
                                  proj_o, bias_o, v_o, seq_o);

    // 5) GRU input gates (both streams, one launch)  M=B*T,N=3H,K=3H
    {
        GemmArgs a0{seq_s, H3, sub_w_ih, H3, sub_b_ih, gi_s, H3};
        GemmArgs a1{seq_o, H3, ob_w_ih,  H3, ob_b_ih,  gi_o, H3};
        dim3 g((H3 + 63) / 64, (Bq * Tt + 127) / 128, 2);
        gemm_tc_dual<<<g, 256>>>(a0, a1, Bq * Tt, H3, H3);
    }

    // 6) fused GRU — whole T-loop, both streams, one launch
    gru_fused<<<dim3(Bq / 8, 2), 256>>>(sub_w_hh, sub_b_hh, ob_w_hh, ob_b_hh,
                                        s_hlen, o_hlen);

    // 7) permuted feature assembly
    feat_kernel<<<Bq, 256>>>(trip, sidx, 0, ent, rel, h_s, feat_s);
    feat_kernel<<<Bq, 256>>>(trip, oidx, 2, ent, rel, h_o, feat_o);

    // 8) prediction GEMMs into d_out (both, one launch)  M=Bq,N=Ee,K=3H
    //    layout: [loss(1) | sub_pred(B*E) | ob_pred(B*E) | o_idx(B) | s_idx(B)]
    {
        GemmArgs a0{feat_s, H3, lin_sub_w, H3, lin_sub_b, out + 1 + (size_t)BE, Ee};
        GemmArgs a1{feat_o, H3, lin_ob_w,  H3, lin_ob_b,  out + 1,              Ee};
        dim3 g((Ee + 63) / 64, (Bq + 127) / 128, 2);
        gemm_tc_dual<<<g, 256>>>(a0, a1, Bq, Ee, H3);
    }

    // 9) CE log-probs + finalize
    ce_kernel<<<Bq, 256>>>(out + 1 + (size_t)BE, trip, sidx, 2, lp0); // ob_pred vs o[s_idx]
    ce_kernel<<<Bq, 256>>>(out + 1,              trip, oidx, 0, lp1); // sub_pred vs s[o_idx]
    finalize_kernel<<<1, 512>>>(out);
}